// round 13
// baseline (speedup 1.0000x reference)
#include <cuda_runtime.h>

#define Bn 4
#define Tn 4096
#define En 1024
#define Hn 64
#define SCALE 0.03125f   // 1024^-0.5
#define LOG2E 1.44269504088896340736f
#define COMP  1.00033857f   // 1 + 2^-11*ln2 : cancels tf32 truncation bias on x

typedef unsigned uu;

// Final projected tensors (tf32 bit patterns, written by merge_kernel):
//  g_q[b][tok][h']  (SCALE*log2e folded via Wq, h sigma-permuted)
//  g_k[b][tok][h']  (h sigma-permuted)
//  g_vt[b][h][tok]  (transposed)
__device__ uu g_q[Bn * Tn * Hn];
__device__ uu g_k[Bn * Tn * Hn];
__device__ uu g_vt[Bn * Hn * Tn];
// W pre-converted to tf32 bits: [m][k][n], m in {q(scaled), k, v}; bias-compensated
__device__ uu g_wt[3 * En * Hn];
// fp32 partials per k-half, already in FINAL layout (permuted / transposed)
__device__ float s_q[2][Bn * Tn * Hn];
__device__ float s_k[2][Bn * Tn * Hn];
__device__ float s_v[2][Bn * Hn * Tn];

__device__ __forceinline__ uu f2tf(float f) {
    uu r; asm("cvt.rna.tf32.f32 %0, %1;" : "=r"(r) : "f"(f)); return r;
}

// D += A(16x8,row) * B(8x8,col), tf32 in, fp32 accum
__device__ __forceinline__ void mma8(float c[4], const uu a[4], const uu b[2]) {
    asm("mma.sync.aligned.m16n8k8.row.col.f32.tf32.tf32.f32 "
        "{%0,%1,%2,%3}, {%4,%5,%6,%7}, {%8,%9}, {%0,%1,%2,%3};"
        : "+f"(c[0]), "+f"(c[1]), "+f"(c[2]), "+f"(c[3])
        : "r"(a[0]), "r"(a[1]), "r"(a[2]), "r"(a[3]), "r"(b[0]), "r"(b[1]));
}

// group-scoped named barrier (128 threads)
__device__ __forceinline__ void barg(int id) {
    asm volatile("bar.sync %0, %1;" :: "r"(id), "r"(128) : "memory");
}

__device__ __forceinline__ void cpa16(void* s, const void* g) {
    unsigned sa = (unsigned)__cvta_generic_to_shared(s);
    asm volatile("cp.async.ca.shared.global [%0], [%1], 16;" :: "r"(sa), "l"(g));
}
__device__ __forceinline__ void cpa_commit() {
    asm volatile("cp.async.commit_group;" ::: "memory");
}
__device__ __forceinline__ void cpa_wait0() {
    asm volatile("cp.async.wait_group 0;" ::: "memory");
}
__device__ __forceinline__ void cpa_wait1() {
    asm volatile("cp.async.wait_group 1;" ::: "memory");
}

// ========== W pre-convert: fp32 -> tf32 bits [m][k][n], scale + bias comp folded ==========
__global__ void wconv_kernel(const float* __restrict__ Wq,
                             const float* __restrict__ Wk,
                             const float* __restrict__ Wv)
{
    int idx = blockIdx.x * 256 + threadIdx.x;      // 0..196607
    int m = idx >> 16, j = idx & 65535;
    const float* W = (m == 0) ? Wq : (m == 1 ? Wk : Wv);
    float sc = (m == 0) ? (SCALE * LOG2E * COMP) : COMP;
    g_wt[idx] = f2tf(W[j] * sc);
}

// ================= QKV projection: k-split, 512 blocks, 3 blocks/SM =================
// Block = (row-tile 64, k-half 512). Traffic-neutral vs full-k; 3x occupancy.
// x staged raw fp32 -> A-frags feed raw bits (truncation compensated via COMP in W).
#define PKC 32
#define XS_ST 36
#define WS_ST 196

__global__ void __launch_bounds__(128, 3) qkv_kernel(const float* __restrict__ x)
{
    extern __shared__ float smf[];
    float* xsb = smf;
    uu* wsb = (uu*)(smf + 2 * 64 * XS_ST);

    const int tid = threadIdx.x;
    const int w = tid >> 5, lane = tid & 31, gr = lane >> 2, t = lane & 3;
    const int row0 = (blockIdx.x >> 1) * 64;
    const int half = blockIdx.x & 1;
    const int kbase = half * 512;

    float acc[4][6][4];
#pragma unroll
    for (int rb = 0; rb < 4; rb++)
#pragma unroll
        for (int nt = 0; nt < 6; nt++)
#pragma unroll
            for (int c = 0; c < 4; c++) acc[rb][nt][c] = 0.f;

    auto issue = [&](int k0, int s) {
        float* xs = xsb + s * 64 * XS_ST;
        uu* ws = wsb + s * PKC * WS_ST;
#pragma unroll
        for (int it = 0; it < 4; it++) {
            int idx = tid + it * 128;
            int r = idx >> 3, c = (idx & 7) * 4;
            cpa16(&xs[r * XS_ST + c], &x[(size_t)(row0 + r) * En + k0 + c]);
        }
#pragma unroll
        for (int it = 0; it < 12; it++) {
            int idx = tid + it * 128;
            int kk = idx / 48, n4 = (idx % 48) * 4;
            int m = n4 >> 6, col = n4 & 63;
            cpa16(&ws[kk * WS_ST + n4], &g_wt[(size_t)m * En * Hn + (size_t)(k0 + kk) * Hn + col]);
        }
    };

    issue(kbase, 0);
    cpa_commit();

    for (int it = 0; it < 512 / PKC; it++) {
        __syncthreads();
        if (it + 1 < 512 / PKC) issue(kbase + (it + 1) * PKC, (it + 1) & 1);
        cpa_commit();
        cpa_wait1();
        __syncthreads();

        const uu* xs = (const uu*)(xsb + (it & 1) * 64 * XS_ST);   // raw f32 bits
        const uu* ws = wsb + (it & 1) * PKC * WS_ST;
#pragma unroll
        for (int kk = 0; kk < PKC / 8; kk++) {
            uu a[4][4];
#pragma unroll
            for (int rb = 0; rb < 4; rb++) {
                int r = rb * 16 + gr;
                a[rb][0] = xs[r * XS_ST + kk * 8 + t];
                a[rb][1] = xs[(r + 8) * XS_ST + kk * 8 + t];
                a[rb][2] = xs[r * XS_ST + kk * 8 + t + 4];
                a[rb][3] = xs[(r + 8) * XS_ST + kk * 8 + t + 4];
            }
#pragma unroll
            for (int nt = 0; nt < 6; nt++) {
                int n0 = w * 48 + nt * 8;
                uu b[2];
                b[0] = ws[(kk * 8 + t) * WS_ST + n0 + gr];
                b[1] = ws[(kk * 8 + t + 4) * WS_ST + n0 + gr];
#pragma unroll
                for (int rb = 0; rb < 4; rb++) mma8(acc[rb][nt], a[rb], b);
            }
        }
    }

    // ---- epilogue: fp32 partials in FINAL layout ----
    const int bb = row0 >> 12;
    const int tok0 = row0 & 4095;
    // sigma position for within-8-block offset 2t: pos(off) = off<4 ? 2*off : 2*(off-4)+1
    const int p0 = (t < 2) ? 4 * t : 4 * t - 7;
    float* sq = s_q[half];
    float* sk = s_k[half];
    float* sv = s_v[half];
#pragma unroll
    for (int nt = 0; nt < 6; nt++) {
        int n = w * 48 + nt * 8 + 2 * t;
        if (n < 128) {
            float* base = (n < 64) ? sq : sk;
            int hb = (n & 63) & ~7;
#pragma unroll
            for (int rb = 0; rb < 4; rb++) {
                size_t r = (size_t)(row0 + rb * 16 + gr);
                base[r * Hn + hb + p0]           = acc[rb][nt][0];
                base[r * Hn + hb + p0 + 2]       = acc[rb][nt][1];
                base[(r + 8) * Hn + hb + p0]     = acc[rb][nt][2];
                base[(r + 8) * Hn + hb + p0 + 2] = acc[rb][nt][3];
            }
        } else {
            int h0 = n - 128;
            float* vr0 = sv + ((size_t)bb * Hn + h0) * Tn;
            float* vr1 = vr0 + Tn;
#pragma unroll
            for (int rb = 0; rb < 4; rb++) {
                int tk = tok0 + rb * 16 + gr;
                vr0[tk]     = acc[rb][nt][0];
                vr1[tk]     = acc[rb][nt][1];
                vr0[tk + 8] = acc[rb][nt][2];
                vr1[tk + 8] = acc[rb][nt][3];
            }
        }
    }
}

// ========== merge: add the two k-half partials, round to tf32 bits ==========
// 3 arrays x 1M floats = 786432 float4 -> grid 3072 x 256
__global__ void merge_kernel()
{
    int idx = blockIdx.x * 256 + threadIdx.x;
    int arr = idx >> 18;              // 262144 float4 per array
    int off = idx & 262143;
    const float4 *pa, *pb;
    uint4* pd;
    if (arr == 0)      { pa = (const float4*)s_q[0]; pb = (const float4*)s_q[1]; pd = (uint4*)g_q; }
    else if (arr == 1) { pa = (const float4*)s_k[0]; pb = (const float4*)s_k[1]; pd = (uint4*)g_k; }
    else               { pa = (const float4*)s_v[0]; pb = (const float4*)s_v[1]; pd = (uint4*)g_vt; }
    float4 a = pa[off], b = pb[off];
    pd[off] = make_uint4(f2tf(a.x + b.x), f2tf(a.y + b.y),
                         f2tf(a.z + b.z), f2tf(a.w + b.w));
}

// ======== Flash attention: 256 blocks, NO-MAX exp2 softmax, rounded P ========
// 3 kt-groups x (2x2) 32x32 warp tiles. p = exp2(s) directly (bounded scores).
#define AS2 72
#define NG 3

__global__ void __launch_bounds__(384, 1) attn_kernel(float* __restrict__ out)
{
    extern __shared__ uu sm[];
    const int tid = threadIdx.x;
    const int w = tid >> 5, lane = tid & 31, gr = lane >> 2, t = lane & 3;
    const int g = w >> 2, wq = w & 3;
    const int rw = wq >> 1, cw = wq & 1;
    const int tg = tid & 127;

    uu* qs  = sm;                                   // strip 0: Q tile
    uu* ksg = sm + (size_t)(1 + g) * 64 * AS2;      // strips 1..3: K per group
    uu* vts = sm + (size_t)(4 + g) * 64 * AS2;      // strips 4..6: V^T per group
    float* Mg = (float*)(sm + (size_t)(1 + 2 * g + cw) * 64 * AS2);  // merge alias

    const int b = blockIdx.x & 3;
    const int qt = 63 - (blockIdx.x >> 2);          // heavy q-tiles launch first
    const uu* kg  = g_k  + (size_t)b * Tn * Hn;
    const uu* vtb = g_vt + (size_t)b * Hn * Tn;

    const int rbase = rw * 32, cbase = cw * 32;

    // Q tile: pure bit-copy (16 KB contiguous)
    const uu* qg = g_q + ((size_t)b * Tn + qt * 64) * Hn;
    for (int idx = tid; idx < 1024; idx += 384)
        cpa16(&qs[(idx >> 4) * AS2 + (idx & 15) * 4], qg + idx * 4);
    cpa_commit();
    cpa_wait0();
    __syncthreads();

    float o[2][8][4];
    float ll[2][2];
#pragma unroll
    for (int rb = 0; rb < 2; rb++) {
        ll[rb][0] = ll[rb][1] = 0.f;
#pragma unroll
        for (int ht = 0; ht < 8; ht++)
#pragma unroll
            for (int c = 0; c < 4; c++) o[rb][ht][c] = 0.f;
    }

    for (int kt = g; kt <= qt; kt += NG) {
        barg(g + 1);   // group's readers done with ksg/vts
        const uu* kp = kg + (size_t)kt * 64 * Hn;
#pragma unroll
        for (int it = 0; it < 8; it++) {
            int idx = tg + it * 128;
            int r = idx >> 4, c4 = (idx & 15) * 4;
            cpa16(&ksg[r * AS2 + c4], kp + idx * 4);
            cpa16(&vts[r * AS2 + c4], vtb + (size_t)r * Tn + kt * 64 + c4);
        }
        cpa_commit();
        cpa_wait0();
        barg(g + 1);   // tile visible to whole group

        // ---- stage 1: S(32x32) = Q K^T (LDS.64 frags; scores in log2 domain) ----
        float s[2][4][4];
#pragma unroll
        for (int rb = 0; rb < 2; rb++)
#pragma unroll
            for (int nt = 0; nt < 4; nt++)
#pragma unroll
                for (int c = 0; c < 4; c++) s[rb][nt][c] = 0.f;
#pragma unroll
        for (int kk = 0; kk < 8; kk++) {
            uu qa[2][4];
#pragma unroll
            for (int rb = 0; rb < 2; rb++) {
                int ra = (rbase + rb * 16 + gr) * AS2 + kk * 8 + 2 * t;
                uint2 u0 = *(const uint2*)&qs[ra];
                uint2 u1 = *(const uint2*)&qs[ra + 8 * AS2];
                qa[rb][0] = u0.x; qa[rb][1] = u1.x;
                qa[rb][2] = u0.y; qa[rb][3] = u1.y;
            }
#pragma unroll
            for (int nt = 0; nt < 4; nt++) {
                uint2 kb = *(const uint2*)&ksg[(cbase + nt * 8 + gr) * AS2 + kk * 8 + 2 * t];
                uu bf[2] = { kb.x, kb.y };
                mma8(s[0][nt], qa[0], bf);
                mma8(s[1][nt], qa[1], bf);
            }
        }

        if (kt == qt) {   // causal mask on diagonal tile
#pragma unroll
            for (int rb = 0; rb < 2; rb++) {
                int r0 = rbase + rb * 16 + gr, r1 = r0 + 8;
#pragma unroll
                for (int nt = 0; nt < 4; nt++) {
                    int c0 = cbase + nt * 8 + 2 * t;
                    if (c0 > r0)     s[rb][nt][0] = -1e30f;
                    if (c0 + 1 > r0) s[rb][nt][1] = -1e30f;
                    if (c0 > r1)     s[rb][nt][2] = -1e30f;
                    if (c0 + 1 > r1) s[rb][nt][3] = -1e30f;
                }
            }
        }

        // ---- no-max softmax: p = exp2(s); masked -> exp2(-1e30) = 0 ----
#pragma unroll
        for (int rb = 0; rb < 2; rb++) {
            float rs0 = 0.f, rs1 = 0.f;
#pragma unroll
            for (int nt = 0; nt < 4; nt++) {
                float p0 = exp2f(s[rb][nt][0]), p1 = exp2f(s[rb][nt][1]);
                float p2 = exp2f(s[rb][nt][2]), p3 = exp2f(s[rb][nt][3]);
                rs0 += p0 + p1; rs1 += p2 + p3;
                s[rb][nt][0] = __uint_as_float(f2tf(p0));
                s[rb][nt][1] = __uint_as_float(f2tf(p1));
                s[rb][nt][2] = __uint_as_float(f2tf(p2));
                s[rb][nt][3] = __uint_as_float(f2tf(p3));
            }
            rs0 += __shfl_xor_sync(~0u, rs0, 1);
            rs0 += __shfl_xor_sync(~0u, rs0, 2);
            rs1 += __shfl_xor_sync(~0u, rs1, 1);
            rs1 += __shfl_xor_sync(~0u, rs1, 2);
            ll[rb][0] += rs0;
            ll[rb][1] += rs1;
        }

        // ---- stage 2: O += P V (P a-frag = S c-frag reordered; V^T LDS.64) ----
#pragma unroll
        for (int kk = 0; kk < 4; kk++) {
            uu pa[2][4];
#pragma unroll
            for (int rb = 0; rb < 2; rb++) {
                pa[rb][0] = __float_as_uint(s[rb][kk][0]);
                pa[rb][1] = __float_as_uint(s[rb][kk][2]);
                pa[rb][2] = __float_as_uint(s[rb][kk][1]);
                pa[rb][3] = __float_as_uint(s[rb][kk][3]);
            }
#pragma unroll
            for (int ht = 0; ht < 8; ht++) {
                uint2 vv = *(const uint2*)&vts[(ht * 8 + gr) * AS2 + cbase + kk * 8 + 2 * t];
                uu vb[2] = { vv.x, vv.y };
                mma8(o[0][ht], pa[0], vb);
                mma8(o[1][ht], pa[1], vb);
            }
        }
    }

    // ---- dump 6 partials into strips 1..6 (staging dead now) ----
    __syncthreads();
#pragma unroll
    for (int rb = 0; rb < 2; rb++) {
        int r0 = rbase + rb * 16 + gr, r1 = r0 + 8;
#pragma unroll
        for (int ht = 0; ht < 8; ht++) {
            *(float2*)&Mg[r0 * AS2 + ht * 8 + 2 * t] = make_float2(o[rb][ht][0], o[rb][ht][1]);
            *(float2*)&Mg[r1 * AS2 + ht * 8 + 2 * t] = make_float2(o[rb][ht][2], o[rb][ht][3]);
        }
        if (t == 0) {
            Mg[r0 * AS2 + 64] = ll[rb][0];
            Mg[r1 * AS2 + 64] = ll[rb][1];
        }
    }
    __syncthreads();

    // ---- combine 6 partials (plain sums), write output ----
    float* ob = out + ((size_t)b * Tn + qt * 64) * Hn;
    for (int idx = tid; idx < 1024; idx += 384) {
        int r = idx >> 4, c4 = (idx & 15) * 4;
        float L = 0.f;
        float4 acc = make_float4(0.f, 0.f, 0.f, 0.f);
#pragma unroll
        for (int i = 0; i < 6; i++) {
            const float* Mi = (const float*)(sm + (size_t)(1 + i) * 64 * AS2);
            L += Mi[r * AS2 + 64];
            float4 v = *(const float4*)&Mi[r * AS2 + c4];
            acc.x += v.x; acc.y += v.y; acc.z += v.z; acc.w += v.w;
        }
        float inv = 1.f / L;
        acc.x *= inv; acc.y *= inv; acc.z *= inv; acc.w *= inv;
        *(float4*)&ob[(size_t)r * Hn + c4] = acc;
    }
}

// ================= launcher =================
extern "C" void kernel_launch(void* const* d_in, const int* in_sizes, int n_in,
                              void* d_out, int out_size)
{
    const float* x  = (const float*)d_in[0];
    const float* Wq = (const float*)d_in[1];
    const float* Wk = (const float*)d_in[2];
    const float* Wv = (const float*)d_in[3];
    float* out = (float*)d_out;

    wconv_kernel<<<768, 256>>>(Wq, Wk, Wv);

    int qkv_smem = 2 * (64 * XS_ST + PKC * WS_ST) * (int)sizeof(float);   // 68608
    cudaFuncSetAttribute(qkv_kernel, cudaFuncAttributeMaxDynamicSharedMemorySize, qkv_smem);
    qkv_kernel<<<512, 128, qkv_smem>>>(x);

    merge_kernel<<<3072, 256>>>();

    int attn_smem = 7 * 64 * AS2 * (int)sizeof(uu);                       // 129024
    cudaFuncSetAttribute(attn_kernel, cudaFuncAttributeMaxDynamicSharedMemorySize, attn_smem);
    attn_kernel<<<Bn * 64, 384, attn_smem>>>(out);
}

// round 14
// speedup vs baseline: 1.1678x; 1.1678x over previous
#include <cuda_runtime.h>

#define Bn 4
#define Tn 4096
#define En 1024
#define Hn 64
#define SCALE 0.03125f   // 1024^-0.5
#define LOG2E 1.44269504088896340736f
#define COMP  1.00033857f   // 1 + 2^-11*ln2 : cancels tf32 truncation bias on x

typedef unsigned uu;

// Projected tensors (tf32 bit patterns, written by qkv_kernel):
//  g_q[b][tok][h']  (SCALE*log2e folded via Wq, h sigma-permuted)
//  g_k[b][tok][h']  (h sigma-permuted)
//  g_vt[b][h][tok]  (transposed)
__device__ uu g_q[Bn * Tn * Hn];
__device__ uu g_k[Bn * Tn * Hn];
__device__ uu g_vt[Bn * Hn * Tn];
// W pre-converted to tf32 bits: [m][k][n], m in {q(scaled), k, v}; bias-compensated
__device__ uu g_wt[3 * En * Hn];

__device__ __forceinline__ uu f2tf(float f) {
    uu r; asm("cvt.rna.tf32.f32 %0, %1;" : "=r"(r) : "f"(f)); return r;
}

// D += A(16x8,row) * B(8x8,col), tf32 in, fp32 accum
__device__ __forceinline__ void mma8(float c[4], const uu a[4], const uu b[2]) {
    asm("mma.sync.aligned.m16n8k8.row.col.f32.tf32.tf32.f32 "
        "{%0,%1,%2,%3}, {%4,%5,%6,%7}, {%8,%9}, {%0,%1,%2,%3};"
        : "+f"(c[0]), "+f"(c[1]), "+f"(c[2]), "+f"(c[3])
        : "r"(a[0]), "r"(a[1]), "r"(a[2]), "r"(a[3]), "r"(b[0]), "r"(b[1]));
}

// group-scoped named barrier (128 threads)
__device__ __forceinline__ void barg(int id) {
    asm volatile("bar.sync %0, %1;" :: "r"(id), "r"(128) : "memory");
}

__device__ __forceinline__ void cpa16(void* s, const void* g) {
    unsigned sa = (unsigned)__cvta_generic_to_shared(s);
    asm volatile("cp.async.ca.shared.global [%0], [%1], 16;" :: "r"(sa), "l"(g));
}
__device__ __forceinline__ void cpa_commit() {
    asm volatile("cp.async.commit_group;" ::: "memory");
}
__device__ __forceinline__ void cpa_wait0() {
    asm volatile("cp.async.wait_group 0;" ::: "memory");
}
__device__ __forceinline__ void cpa_wait1() {
    asm volatile("cp.async.wait_group 1;" ::: "memory");
}

// ========== W pre-convert: fp32 -> tf32 bits [m][k][n], scale + bias comp folded ==========
__global__ void wconv_kernel(const float* __restrict__ Wq,
                             const float* __restrict__ Wk,
                             const float* __restrict__ Wv)
{
    int idx = blockIdx.x * 256 + threadIdx.x;      // 0..196607
    int m = idx >> 16, j = idx & 65535;
    const float* W = (m == 0) ? Wq : (m == 1 ? Wk : Wv);
    float sc = (m == 0) ? (SCALE * LOG2E * COMP) : COMP;
    g_wt[idx] = f2tf(W[j] * sc);
}

// ================= QKV projection: n-split, grid 512, ~4 blocks/SM =================
// Block = (64 rows, n-half: 96 of 192 cols). W L2 traffic unchanged (each block
// reads only its W half); x re-read hits L2 (both halves co-resident).
// x staged raw fp32 -> A-frags feed raw bits (truncation compensated via COMP in W).
#define PKC 32
#define XS_ST 36
#define WST2 100   // 96 cols + 4 pad; mod 32 == 4, mod 4 == 0

__global__ void __launch_bounds__(128, 4) qkv_kernel(const float* __restrict__ x)
{
    extern __shared__ float smf[];
    float* xsb = smf;                           // 2 stages x [64][XS_ST]
    uu* wsb = (uu*)(smf + 2 * 64 * XS_ST);      // 2 stages x [PKC][WST2]

    const int tid = threadIdx.x;
    const int w = tid >> 5, lane = tid & 31, gr = lane >> 2, t = lane & 3;
    const int row0 = (blockIdx.x >> 1) * 64;
    const int nbase = (blockIdx.x & 1) * 96;

    float acc[4][3][4];
#pragma unroll
    for (int rb = 0; rb < 4; rb++)
#pragma unroll
        for (int nt = 0; nt < 3; nt++)
#pragma unroll
            for (int c = 0; c < 4; c++) acc[rb][nt][c] = 0.f;

    auto issue = [&](int k0, int s) {
        float* xs = xsb + s * 64 * XS_ST;
        uu* ws = wsb + s * PKC * WST2;
#pragma unroll
        for (int it = 0; it < 4; it++) {            // x: 512 float4
            int idx = tid + it * 128;
            int r = idx >> 3, c = (idx & 7) * 4;
            cpa16(&xs[r * XS_ST + c], &x[(size_t)(row0 + r) * En + k0 + c]);
        }
#pragma unroll
        for (int it = 0; it < 6; it++) {            // W: 32k x 96n = 768 float4
            int idx = tid + it * 128;
            int kk = idx / 24, n4 = (idx % 24) * 4;
            int cg = nbase + n4;                    // global col 0..191
            int m = cg >> 6, col = cg & 63;
            cpa16(&ws[kk * WST2 + n4], &g_wt[(size_t)m * En * Hn + (size_t)(k0 + kk) * Hn + col]);
        }
    };

    issue(0, 0);
    cpa_commit();

    for (int it = 0; it < En / PKC; it++) {
        __syncthreads();
        if (it + 1 < En / PKC) issue((it + 1) * PKC, (it + 1) & 1);
        cpa_commit();
        cpa_wait1();
        __syncthreads();

        const uu* xs = (const uu*)(xsb + (it & 1) * 64 * XS_ST);   // raw f32 bits
        const uu* ws = wsb + (it & 1) * PKC * WST2;
#pragma unroll
        for (int kk = 0; kk < PKC / 8; kk++) {
            uu a[4][4];
#pragma unroll
            for (int rb = 0; rb < 4; rb++) {
                int r = rb * 16 + gr;
                a[rb][0] = xs[r * XS_ST + kk * 8 + t];
                a[rb][1] = xs[(r + 8) * XS_ST + kk * 8 + t];
                a[rb][2] = xs[r * XS_ST + kk * 8 + t + 4];
                a[rb][3] = xs[(r + 8) * XS_ST + kk * 8 + t + 4];
            }
#pragma unroll
            for (int nt = 0; nt < 3; nt++) {
                int n0 = w * 24 + nt * 8;
                uu b[2];
                b[0] = ws[(kk * 8 + t) * WST2 + n0 + gr];
                b[1] = ws[(kk * 8 + t + 4) * WST2 + n0 + gr];
#pragma unroll
                for (int rb = 0; rb < 4; rb++) mma8(acc[rb][nt], a[rb], b);
            }
        }
    }

    // ---- epilogue: tf32 bits directly to final layout ----
    const int bb = row0 >> 12;
    const int tok0 = row0 & 4095;
    // sigma position for within-8-block offset 2t: pos(off) = off<4 ? 2*off : 2*(off-4)+1
    const int p0 = (t < 2) ? 4 * t : 4 * t - 7;
#pragma unroll
    for (int nt = 0; nt < 3; nt++) {
        int n = nbase + w * 24 + nt * 8 + 2 * t;
        if (n < 128) {
            uu* base = (n < 64) ? g_q : g_k;
            int hb = (n & 63) & ~7;
#pragma unroll
            for (int rb = 0; rb < 4; rb++) {
                size_t r = (size_t)(row0 + rb * 16 + gr);
                base[r * Hn + hb + p0]           = f2tf(acc[rb][nt][0]);
                base[r * Hn + hb + p0 + 2]       = f2tf(acc[rb][nt][1]);
                base[(r + 8) * Hn + hb + p0]     = f2tf(acc[rb][nt][2]);
                base[(r + 8) * Hn + hb + p0 + 2] = f2tf(acc[rb][nt][3]);
            }
        } else {
            int h0 = n - 128;
            uu* vr0 = g_vt + ((size_t)bb * Hn + h0) * Tn;
            uu* vr1 = vr0 + Tn;
#pragma unroll
            for (int rb = 0; rb < 4; rb++) {
                int tk = tok0 + rb * 16 + gr;
                vr0[tk]     = f2tf(acc[rb][nt][0]);
                vr1[tk]     = f2tf(acc[rb][nt][1]);
                vr0[tk + 8] = f2tf(acc[rb][nt][2]);
                vr1[tk + 8] = f2tf(acc[rb][nt][3]);
            }
        }
    }
}

// ======== Flash attention (R13 verbatim): 256 blocks, NO-MAX exp2 softmax, rounded P ========
#define AS2 72
#define NG 3

__global__ void __launch_bounds__(384, 1) attn_kernel(float* __restrict__ out)
{
    extern __shared__ uu sm[];
    const int tid = threadIdx.x;
    const int w = tid >> 5, lane = tid & 31, gr = lane >> 2, t = lane & 3;
    const int g = w >> 2, wq = w & 3;
    const int rw = wq >> 1, cw = wq & 1;
    const int tg = tid & 127;

    uu* qs  = sm;                                   // strip 0: Q tile
    uu* ksg = sm + (size_t)(1 + g) * 64 * AS2;      // strips 1..3: K per group
    uu* vts = sm + (size_t)(4 + g) * 64 * AS2;      // strips 4..6: V^T per group
    float* Mg = (float*)(sm + (size_t)(1 + 2 * g + cw) * 64 * AS2);  // merge alias

    const int b = blockIdx.x & 3;
    const int qt = 63 - (blockIdx.x >> 2);          // heavy q-tiles launch first
    const uu* kg  = g_k  + (size_t)b * Tn * Hn;
    const uu* vtb = g_vt + (size_t)b * Hn * Tn;

    const int rbase = rw * 32, cbase = cw * 32;

    // Q tile: pure bit-copy (16 KB contiguous)
    const uu* qg = g_q + ((size_t)b * Tn + qt * 64) * Hn;
    for (int idx = tid; idx < 1024; idx += 384)
        cpa16(&qs[(idx >> 4) * AS2 + (idx & 15) * 4], qg + idx * 4);
    cpa_commit();
    cpa_wait0();
    __syncthreads();

    float o[2][8][4];
    float ll[2][2];
#pragma unroll
    for (int rb = 0; rb < 2; rb++) {
        ll[rb][0] = ll[rb][1] = 0.f;
#pragma unroll
        for (int ht = 0; ht < 8; ht++)
#pragma unroll
            for (int c = 0; c < 4; c++) o[rb][ht][c] = 0.f;
    }

    for (int kt = g; kt <= qt; kt += NG) {
        barg(g + 1);   // group's readers done with ksg/vts
        const uu* kp = kg + (size_t)kt * 64 * Hn;
#pragma unroll
        for (int it = 0; it < 8; it++) {
            int idx = tg + it * 128;
            int r = idx >> 4, c4 = (idx & 15) * 4;
            cpa16(&ksg[r * AS2 + c4], kp + idx * 4);
            cpa16(&vts[r * AS2 + c4], vtb + (size_t)r * Tn + kt * 64 + c4);
        }
        cpa_commit();
        cpa_wait0();
        barg(g + 1);   // tile visible to whole group

        // ---- stage 1: S(32x32) = Q K^T (LDS.64 frags; scores in log2 domain) ----
        float s[2][4][4];
#pragma unroll
        for (int rb = 0; rb < 2; rb++)
#pragma unroll
            for (int nt = 0; nt < 4; nt++)
#pragma unroll
                for (int c = 0; c < 4; c++) s[rb][nt][c] = 0.f;
#pragma unroll
        for (int kk = 0; kk < 8; kk++) {
            uu qa[2][4];
#pragma unroll
            for (int rb = 0; rb < 2; rb++) {
                int ra = (rbase + rb * 16 + gr) * AS2 + kk * 8 + 2 * t;
                uint2 u0 = *(const uint2*)&qs[ra];
                uint2 u1 = *(const uint2*)&qs[ra + 8 * AS2];
                qa[rb][0] = u0.x; qa[rb][1] = u1.x;
                qa[rb][2] = u0.y; qa[rb][3] = u1.y;
            }
#pragma unroll
            for (int nt = 0; nt < 4; nt++) {
                uint2 kb = *(const uint2*)&ksg[(cbase + nt * 8 + gr) * AS2 + kk * 8 + 2 * t];
                uu bf[2] = { kb.x, kb.y };
                mma8(s[0][nt], qa[0], bf);
                mma8(s[1][nt], qa[1], bf);
            }
        }

        if (kt == qt) {   // causal mask on diagonal tile
#pragma unroll
            for (int rb = 0; rb < 2; rb++) {
                int r0 = rbase + rb * 16 + gr, r1 = r0 + 8;
#pragma unroll
                for (int nt = 0; nt < 4; nt++) {
                    int c0 = cbase + nt * 8 + 2 * t;
                    if (c0 > r0)     s[rb][nt][0] = -1e30f;
                    if (c0 + 1 > r0) s[rb][nt][1] = -1e30f;
                    if (c0 > r1)     s[rb][nt][2] = -1e30f;
                    if (c0 + 1 > r1) s[rb][nt][3] = -1e30f;
                }
            }
        }

        // ---- no-max softmax: p = exp2(s); masked -> exp2(-1e30) = 0 ----
#pragma unroll
        for (int rb = 0; rb < 2; rb++) {
            float rs0 = 0.f, rs1 = 0.f;
#pragma unroll
            for (int nt = 0; nt < 4; nt++) {
                float p0 = exp2f(s[rb][nt][0]), p1 = exp2f(s[rb][nt][1]);
                float p2 = exp2f(s[rb][nt][2]), p3 = exp2f(s[rb][nt][3]);
                rs0 += p0 + p1; rs1 += p2 + p3;
                s[rb][nt][0] = __uint_as_float(f2tf(p0));
                s[rb][nt][1] = __uint_as_float(f2tf(p1));
                s[rb][nt][2] = __uint_as_float(f2tf(p2));
                s[rb][nt][3] = __uint_as_float(f2tf(p3));
            }
            rs0 += __shfl_xor_sync(~0u, rs0, 1);
            rs0 += __shfl_xor_sync(~0u, rs0, 2);
            rs1 += __shfl_xor_sync(~0u, rs1, 1);
            rs1 += __shfl_xor_sync(~0u, rs1, 2);
            ll[rb][0] += rs0;
            ll[rb][1] += rs1;
        }

        // ---- stage 2: O += P V (P a-frag = S c-frag reordered; V^T LDS.64) ----
#pragma unroll
        for (int kk = 0; kk < 4; kk++) {
            uu pa[2][4];
#pragma unroll
            for (int rb = 0; rb < 2; rb++) {
                pa[rb][0] = __float_as_uint(s[rb][kk][0]);
                pa[rb][1] = __float_as_uint(s[rb][kk][2]);
                pa[rb][2] = __float_as_uint(s[rb][kk][1]);
                pa[rb][3] = __float_as_uint(s[rb][kk][3]);
            }
#pragma unroll
            for (int ht = 0; ht < 8; ht++) {
                uint2 vv = *(const uint2*)&vts[(ht * 8 + gr) * AS2 + cbase + kk * 8 + 2 * t];
                uu vb[2] = { vv.x, vv.y };
                mma8(o[0][ht], pa[0], vb);
                mma8(o[1][ht], pa[1], vb);
            }
        }
    }

    // ---- dump 6 partials into strips 1..6 (staging dead now) ----
    __syncthreads();
#pragma unroll
    for (int rb = 0; rb < 2; rb++) {
        int r0 = rbase + rb * 16 + gr, r1 = r0 + 8;
#pragma unroll
        for (int ht = 0; ht < 8; ht++) {
            *(float2*)&Mg[r0 * AS2 + ht * 8 + 2 * t] = make_float2(o[rb][ht][0], o[rb][ht][1]);
            *(float2*)&Mg[r1 * AS2 + ht * 8 + 2 * t] = make_float2(o[rb][ht][2], o[rb][ht][3]);
        }
        if (t == 0) {
            Mg[r0 * AS2 + 64] = ll[rb][0];
            Mg[r1 * AS2 + 64] = ll[rb][1];
        }
    }
    __syncthreads();

    // ---- combine 6 partials (plain sums), write output ----
    float* ob = out + ((size_t)b * Tn + qt * 64) * Hn;
    for (int idx = tid; idx < 1024; idx += 384) {
        int r = idx >> 4, c4 = (idx & 15) * 4;
        float L = 0.f;
        float4 acc = make_float4(0.f, 0.f, 0.f, 0.f);
#pragma unroll
        for (int i = 0; i < 6; i++) {
            const float* Mi = (const float*)(sm + (size_t)(1 + i) * 64 * AS2);
            L += Mi[r * AS2 + 64];
            float4 v = *(const float4*)&Mi[r * AS2 + c4];
            acc.x += v.x; acc.y += v.y; acc.z += v.z; acc.w += v.w;
        }
        float inv = 1.f / L;
        acc.x *= inv; acc.y *= inv; acc.z *= inv; acc.w *= inv;
        *(float4*)&ob[(size_t)r * Hn + c4] = acc;
    }
}

// ================= launcher =================
extern "C" void kernel_launch(void* const* d_in, const int* in_sizes, int n_in,
                              void* d_out, int out_size)
{
    const float* x  = (const float*)d_in[0];
    const float* Wq = (const float*)d_in[1];
    const float* Wk = (const float*)d_in[2];
    const float* Wv = (const float*)d_in[3];
    float* out = (float*)d_out;

    wconv_kernel<<<768, 256>>>(Wq, Wk, Wv);

    int qkv_smem = 2 * (64 * XS_ST + PKC * WST2) * (int)sizeof(float);   // 44032
    cudaFuncSetAttribute(qkv_kernel, cudaFuncAttributeMaxDynamicSharedMemorySize, qkv_smem);
    qkv_kernel<<<512, 128, qkv_smem>>>(x);

    int attn_smem = 7 * 64 * AS2 * (int)sizeof(uu);                      // 129024
    cudaFuncSetAttribute(attn_kernel, cudaFuncAttributeMaxDynamicSharedMemorySize, attn_smem);
    attn_kernel<<<Bn * 64, 384, attn_smem>>>(out);
}

// round 15
// speedup vs baseline: 1.2891x; 1.1038x over previous
#include <cuda_runtime.h>

#define Bn 4
#define Tn 4096
#define En 1024
#define Hn 64
#define SCALE 0.03125f   // 1024^-0.5
#define LOG2E 1.44269504088896340736f
#define COMP  1.00033857f   // 1 + 2^-11*ln2 : cancels tf32 truncation bias on raw-bit x

typedef unsigned uu;

// Projected tensors (tf32 bit patterns, written by qkv_kernel):
//  g_q[b][tok][h']  (SCALE*log2e folded via Wq, h sigma-permuted)
//  g_k[b][tok][h']  (h sigma-permuted)
//  g_vt[b][h][tok]  (transposed)
__device__ uu g_q[Bn * Tn * Hn];
__device__ uu g_k[Bn * Tn * Hn];
__device__ uu g_vt[Bn * Hn * Tn];
// W pre-converted to tf32 bits: [m][k][n], m in {q(scaled), k, v}; bias-compensated
__device__ uu g_wt[3 * En * Hn];

__device__ __forceinline__ uu f2tf(float f) {
    uu r; asm("cvt.rna.tf32.f32 %0, %1;" : "=r"(r) : "f"(f)); return r;
}
__device__ __forceinline__ float ex2(float x) {
    float r; asm("ex2.approx.f32 %0, %1;" : "=f"(r) : "f"(x)); return r;
}

// D += A(16x8,row) * B(8x8,col), tf32 in, fp32 accum
__device__ __forceinline__ void mma8(float c[4], const uu a[4], const uu b[2]) {
    asm("mma.sync.aligned.m16n8k8.row.col.f32.tf32.tf32.f32 "
        "{%0,%1,%2,%3}, {%4,%5,%6,%7}, {%8,%9}, {%0,%1,%2,%3};"
        : "+f"(c[0]), "+f"(c[1]), "+f"(c[2]), "+f"(c[3])
        : "r"(a[0]), "r"(a[1]), "r"(a[2]), "r"(a[3]), "r"(b[0]), "r"(b[1]));
}

// group-scoped named barrier (128 threads)
__device__ __forceinline__ void barg(int id) {
    asm volatile("bar.sync %0, %1;" :: "r"(id), "r"(128) : "memory");
}

__device__ __forceinline__ void cpa16(void* s, const void* g) {
    unsigned sa = (unsigned)__cvta_generic_to_shared(s);
    asm volatile("cp.async.ca.shared.global [%0], [%1], 16;" :: "r"(sa), "l"(g));
}
__device__ __forceinline__ void cpa_commit() {
    asm volatile("cp.async.commit_group;" ::: "memory");
}
__device__ __forceinline__ void cpa_wait0() {
    asm volatile("cp.async.wait_group 0;" ::: "memory");
}
__device__ __forceinline__ void cpa_wait1() {
    asm volatile("cp.async.wait_group 1;" ::: "memory");
}

// ========== W pre-convert: fp32 -> tf32 bits [m][k][n], scale + bias comp folded ==========
__global__ void wconv_kernel(const float* __restrict__ Wq,
                             const float* __restrict__ Wk,
                             const float* __restrict__ Wv)
{
    int idx = blockIdx.x * 256 + threadIdx.x;      // 0..196607
    int m = idx >> 16, j = idx & 65535;
    const float* W = (m == 0) ? Wq : (m == 1 ? Wk : Wv);
    float sc = (m == 0) ? (SCALE * LOG2E * COMP) : COMP;
    g_wt[idx] = f2tf(W[j] * sc);
}

// ================= QKV projection (R11 config — measured best) =================
// grid 256, 128 thr, 2 blocks/SM. x staged raw fp32; A-frags feed raw f32 bits
// (tf32 hw truncation, compensated by COMP folded into W).
#define PKC 32
#define XS_ST 36
#define WS_ST 196

__global__ void __launch_bounds__(128, 2) qkv_kernel(const float* __restrict__ x)
{
    extern __shared__ float smf[];
    float* xsb = smf;
    uu* wsb = (uu*)(smf + 2 * 64 * XS_ST);

    const int tid = threadIdx.x;
    const int w = tid >> 5, lane = tid & 31, gr = lane >> 2, t = lane & 3;
    const int row0 = blockIdx.x * 64;

    float acc[4][6][4];
#pragma unroll
    for (int rb = 0; rb < 4; rb++)
#pragma unroll
        for (int nt = 0; nt < 6; nt++)
#pragma unroll
            for (int c = 0; c < 4; c++) acc[rb][nt][c] = 0.f;

    auto issue = [&](int k0, int s) {
        float* xs = xsb + s * 64 * XS_ST;
        uu* ws = wsb + s * PKC * WS_ST;
#pragma unroll
        for (int it = 0; it < 4; it++) {
            int idx = tid + it * 128;
            int r = idx >> 3, c = (idx & 7) * 4;
            cpa16(&xs[r * XS_ST + c], &x[(size_t)(row0 + r) * En + k0 + c]);
        }
#pragma unroll
        for (int it = 0; it < 12; it++) {
            int idx = tid + it * 128;
            int kk = idx / 48, n4 = (idx % 48) * 4;
            int m = n4 >> 6, col = n4 & 63;
            cpa16(&ws[kk * WS_ST + n4], &g_wt[(size_t)m * En * Hn + (size_t)(k0 + kk) * Hn + col]);
        }
    };

    issue(0, 0);
    cpa_commit();

    for (int it = 0; it < En / PKC; it++) {
        __syncthreads();
        if (it + 1 < En / PKC) issue((it + 1) * PKC, (it + 1) & 1);
        cpa_commit();
        cpa_wait1();
        __syncthreads();

        const uu* xs = (const uu*)(xsb + (it & 1) * 64 * XS_ST);   // raw f32 bits
        const uu* ws = wsb + (it & 1) * PKC * WS_ST;
#pragma unroll
        for (int kk = 0; kk < PKC / 8; kk++) {
            uu a[4][4];
#pragma unroll
            for (int rb = 0; rb < 4; rb++) {
                int r = rb * 16 + gr;
                a[rb][0] = xs[r * XS_ST + kk * 8 + t];
                a[rb][1] = xs[(r + 8) * XS_ST + kk * 8 + t];
                a[rb][2] = xs[r * XS_ST + kk * 8 + t + 4];
                a[rb][3] = xs[(r + 8) * XS_ST + kk * 8 + t + 4];
            }
#pragma unroll
            for (int nt = 0; nt < 6; nt++) {
                int n0 = w * 48 + nt * 8;
                uu b[2];
                b[0] = ws[(kk * 8 + t) * WS_ST + n0 + gr];
                b[1] = ws[(kk * 8 + t + 4) * WS_ST + n0 + gr];
#pragma unroll
                for (int rb = 0; rb < 4; rb++) mma8(acc[rb][nt], a[rb], b);
            }
        }
    }

    // ---- epilogue: tf32 bits directly to final layout ----
    const int bb = row0 >> 12;
    const int tok0 = row0 & 4095;
    // sigma position for within-8-block offset 2t: pos(off) = off<4 ? 2*off : 2*(off-4)+1
    const int p0 = (t < 2) ? 4 * t : 4 * t - 7;
#pragma unroll
    for (int nt = 0; nt < 6; nt++) {
        int n = w * 48 + nt * 8 + 2 * t;
        if (n < 128) {
            uu* base = (n < 64) ? g_q : g_k;
            int hb = (n & 63) & ~7;
#pragma unroll
            for (int rb = 0; rb < 4; rb++) {
                size_t r = (size_t)(row0 + rb * 16 + gr);
                base[r * Hn + hb + p0]           = f2tf(acc[rb][nt][0]);
                base[r * Hn + hb + p0 + 2]       = f2tf(acc[rb][nt][1]);
                base[(r + 8) * Hn + hb + p0]     = f2tf(acc[rb][nt][2]);
                base[(r + 8) * Hn + hb + p0 + 2] = f2tf(acc[rb][nt][3]);
            }
        } else {
            int h0 = n - 128;
            uu* vr0 = g_vt + ((size_t)bb * Hn + h0) * Tn;
            uu* vr1 = vr0 + Tn;
#pragma unroll
            for (int rb = 0; rb < 4; rb++) {
                int tk = tok0 + rb * 16 + gr;
                vr0[tk]     = f2tf(acc[rb][nt][0]);
                vr1[tk]     = f2tf(acc[rb][nt][1]);
                vr0[tk + 8] = f2tf(acc[rb][nt][2]);
                vr1[tk + 8] = f2tf(acc[rb][nt][3]);
            }
        }
    }
}

// ======== Flash attention: 256 blocks, NO-MAX softmax via ex2.approx, rounded P ========
// 3 kt-groups x (2x2) 32x32 warp tiles. p = ex2(s) directly (bounded scores);
// masked entries: ex2(-1e30) = 0.
#define AS2 72
#define NG 3

__global__ void __launch_bounds__(384, 1) attn_kernel(float* __restrict__ out)
{
    extern __shared__ uu sm[];
    const int tid = threadIdx.x;
    const int w = tid >> 5, lane = tid & 31, gr = lane >> 2, t = lane & 3;
    const int g = w >> 2, wq = w & 3;
    const int rw = wq >> 1, cw = wq & 1;
    const int tg = tid & 127;

    uu* qs  = sm;                                   // strip 0: Q tile
    uu* ksg = sm + (size_t)(1 + g) * 64 * AS2;      // strips 1..3: K per group
    uu* vts = sm + (size_t)(4 + g) * 64 * AS2;      // strips 4..6: V^T per group
    float* Mg = (float*)(sm + (size_t)(1 + 2 * g + cw) * 64 * AS2);  // merge alias

    const int b = blockIdx.x & 3;
    const int qt = 63 - (blockIdx.x >> 2);          // heavy q-tiles launch first
    const uu* kg  = g_k  + (size_t)b * Tn * Hn;
    const uu* vtb = g_vt + (size_t)b * Hn * Tn;

    const int rbase = rw * 32, cbase = cw * 32;

    // Q tile: pure bit-copy (16 KB contiguous)
    const uu* qg = g_q + ((size_t)b * Tn + qt * 64) * Hn;
    for (int idx = tid; idx < 1024; idx += 384)
        cpa16(&qs[(idx >> 4) * AS2 + (idx & 15) * 4], qg + idx * 4);
    cpa_commit();
    cpa_wait0();
    __syncthreads();

    float o[2][8][4];
    float ll[2][2];
#pragma unroll
    for (int rb = 0; rb < 2; rb++) {
        ll[rb][0] = ll[rb][1] = 0.f;
#pragma unroll
        for (int ht = 0; ht < 8; ht++)
#pragma unroll
            for (int c = 0; c < 4; c++) o[rb][ht][c] = 0.f;
    }

    for (int kt = g; kt <= qt; kt += NG) {
        barg(g + 1);   // group's readers done with ksg/vts
        const uu* kp = kg + (size_t)kt * 64 * Hn;
#pragma unroll
        for (int it = 0; it < 8; it++) {
            int idx = tg + it * 128;
            int r = idx >> 4, c4 = (idx & 15) * 4;
            cpa16(&ksg[r * AS2 + c4], kp + idx * 4);
            cpa16(&vts[r * AS2 + c4], vtb + (size_t)r * Tn + kt * 64 + c4);
        }
        cpa_commit();
        cpa_wait0();
        barg(g + 1);   // tile visible to whole group

        // ---- stage 1: S(32x32) = Q K^T (LDS.64 frags; scores in log2 domain) ----
        float s[2][4][4];
#pragma unroll
        for (int rb = 0; rb < 2; rb++)
#pragma unroll
            for (int nt = 0; nt < 4; nt++)
#pragma unroll
                for (int c = 0; c < 4; c++) s[rb][nt][c] = 0.f;
#pragma unroll
        for (int kk = 0; kk < 8; kk++) {
            uu qa[2][4];
#pragma unroll
            for (int rb = 0; rb < 2; rb++) {
                int ra = (rbase + rb * 16 + gr) * AS2 + kk * 8 + 2 * t;
                uint2 u0 = *(const uint2*)&qs[ra];
                uint2 u1 = *(const uint2*)&qs[ra + 8 * AS2];
                qa[rb][0] = u0.x; qa[rb][1] = u1.x;
                qa[rb][2] = u0.y; qa[rb][3] = u1.y;
            }
#pragma unroll
            for (int nt = 0; nt < 4; nt++) {
                uint2 kb = *(const uint2*)&ksg[(cbase + nt * 8 + gr) * AS2 + kk * 8 + 2 * t];
                uu bf[2] = { kb.x, kb.y };
                mma8(s[0][nt], qa[0], bf);
                mma8(s[1][nt], qa[1], bf);
            }
        }

        if (kt == qt) {   // causal mask on diagonal tile
#pragma unroll
            for (int rb = 0; rb < 2; rb++) {
                int r0 = rbase + rb * 16 + gr, r1 = r0 + 8;
#pragma unroll
                for (int nt = 0; nt < 4; nt++) {
                    int c0 = cbase + nt * 8 + 2 * t;
                    if (c0 > r0)     s[rb][nt][0] = -1e30f;
                    if (c0 + 1 > r0) s[rb][nt][1] = -1e30f;
                    if (c0 > r1)     s[rb][nt][2] = -1e30f;
                    if (c0 + 1 > r1) s[rb][nt][3] = -1e30f;
                }
            }
        }

        // ---- no-max softmax: p = ex2(s) (MUFU.EX2); masked -> 0 ----
#pragma unroll
        for (int rb = 0; rb < 2; rb++) {
            float rs0 = 0.f, rs1 = 0.f;
#pragma unroll
            for (int nt = 0; nt < 4; nt++) {
                float p0 = ex2(s[rb][nt][0]), p1 = ex2(s[rb][nt][1]);
                float p2 = ex2(s[rb][nt][2]), p3 = ex2(s[rb][nt][3]);
                rs0 += p0 + p1; rs1 += p2 + p3;
                s[rb][nt][0] = __uint_as_float(f2tf(p0));
                s[rb][nt][1] = __uint_as_float(f2tf(p1));
                s[rb][nt][2] = __uint_as_float(f2tf(p2));
                s[rb][nt][3] = __uint_as_float(f2tf(p3));
            }
            rs0 += __shfl_xor_sync(~0u, rs0, 1);
            rs0 += __shfl_xor_sync(~0u, rs0, 2);
            rs1 += __shfl_xor_sync(~0u, rs1, 1);
            rs1 += __shfl_xor_sync(~0u, rs1, 2);
            ll[rb][0] += rs0;
            ll[rb][1] += rs1;
        }

        // ---- stage 2: O += P V (P a-frag = S c-frag reordered; V^T LDS.64) ----
#pragma unroll
        for (int kk = 0; kk < 4; kk++) {
            uu pa[2][4];
#pragma unroll
            for (int rb = 0; rb < 2; rb++) {
                pa[rb][0] = __float_as_uint(s[rb][kk][0]);
                pa[rb][1] = __float_as_uint(s[rb][kk][2]);
                pa[rb][2] = __float_as_uint(s[rb][kk][1]);
                pa[rb][3] = __float_as_uint(s[rb][kk][3]);
            }
#pragma unroll
            for (int ht = 0; ht < 8; ht++) {
                uint2 vv = *(const uint2*)&vts[(ht * 8 + gr) * AS2 + cbase + kk * 8 + 2 * t];
                uu vb[2] = { vv.x, vv.y };
                mma8(o[0][ht], pa[0], vb);
                mma8(o[1][ht], pa[1], vb);
            }
        }
    }

    // ---- dump 6 partials into strips 1..6 (staging dead now) ----
    __syncthreads();
#pragma unroll
    for (int rb = 0; rb < 2; rb++) {
        int r0 = rbase + rb * 16 + gr, r1 = r0 + 8;
#pragma unroll
        for (int ht = 0; ht < 8; ht++) {
            *(float2*)&Mg[r0 * AS2 + ht * 8 + 2 * t] = make_float2(o[rb][ht][0], o[rb][ht][1]);
            *(float2*)&Mg[r1 * AS2 + ht * 8 + 2 * t] = make_float2(o[rb][ht][2], o[rb][ht][3]);
        }
        if (t == 0) {
            Mg[r0 * AS2 + 64] = ll[rb][0];
            Mg[r1 * AS2 + 64] = ll[rb][1];
        }
    }
    __syncthreads();

    // ---- combine 6 partials (plain sums), write output ----
    float* ob = out + ((size_t)b * Tn + qt * 64) * Hn;
    for (int idx = tid; idx < 1024; idx += 384) {
        int r = idx >> 4, c4 = (idx & 15) * 4;
        float L = 0.f;
        float4 acc = make_float4(0.f, 0.f, 0.f, 0.f);
#pragma unroll
        for (int i = 0; i < 6; i++) {
            const float* Mi = (const float*)(sm + (size_t)(1 + i) * 64 * AS2);
            L += Mi[r * AS2 + 64];
            float4 v = *(const float4*)&Mi[r * AS2 + c4];
            acc.x += v.x; acc.y += v.y; acc.z += v.z; acc.w += v.w;
        }
        float inv = 1.f / L;
        acc.x *= inv; acc.y *= inv; acc.z *= inv; acc.w *= inv;
        *(float4*)&ob[(size_t)r * Hn + c4] = acc;
    }
}

// ================= launcher =================
extern "C" void kernel_launch(void* const* d_in, const int* in_sizes, int n_in,
                              void* d_out, int out_size)
{
    const float* x  = (const float*)d_in[0];
    const float* Wq = (const float*)d_in[1];
    const float* Wk = (const float*)d_in[2];
    const float* Wv = (const float*)d_in[3];
    float* out = (float*)d_out;

    wconv_kernel<<<768, 256>>>(Wq, Wk, Wv);

    int qkv_smem = 2 * (64 * XS_ST + PKC * WS_ST) * (int)sizeof(float);   // 68608
    cudaFuncSetAttribute(qkv_kernel, cudaFuncAttributeMaxDynamicSharedMemorySize, qkv_smem);
    qkv_kernel<<<(Bn * Tn) / 64, 128, qkv_smem>>>(x);

    int attn_smem = 7 * 64 * AS2 * (int)sizeof(uu);                       // 129024
    cudaFuncSetAttribute(attn_kernel, cudaFuncAttributeMaxDynamicSharedMemorySize, attn_smem);
    attn_kernel<<<Bn * 64, 384, attn_smem>>>(out);
}

// round 16
// speedup vs baseline: 1.6369x; 1.2698x over previous
#include <cuda_runtime.h>

#define Bn 4
#define Tn 4096
#define En 1024
#define Hn 64
#define SCALE 0.03125f   // 1024^-0.5
#define LOG2E 1.44269504088896340736f
#define COMP  1.00033857f   // 1 + 2^-11*ln2 : cancels tf32 truncation bias on raw-bit x

typedef unsigned uu;

// Projected tensors as fp16x2 words (written by qkv_kernel epilogue):
//  g_q16[b][tok][32w]  (SCALE*log2e folded, h word-sigma-permuted, pairs along h)
//  g_k16[b][tok][32w]  (h word-sigma-permuted, pairs along h)
//  g_vt16[b][h][2048w] (transposed, pairs along tokens, token word-sigma-permuted)
__device__ uu g_q16[Bn * Tn * 32];
__device__ uu g_k16[Bn * Tn * 32];
__device__ uu g_vt16[Bn * Hn * (Tn / 2)];
// W pre-converted to tf32 bits for the qkv mainloop: [m][k][n]
__device__ uu g_wt[3 * En * Hn];

__device__ __forceinline__ uu f2tf(float f) {
    uu r; asm("cvt.rna.tf32.f32 %0, %1;" : "=r"(r) : "f"(f)); return r;
}
__device__ __forceinline__ float ex2(float x) {
    float r; asm("ex2.approx.f32 %0, %1;" : "=f"(r) : "f"(x)); return r;
}
// pack two f32 into f16x2 (first src -> upper half; convention consistent everywhere)
__device__ __forceinline__ uu pkf16(float hi, float lo) {
    uu r; asm("cvt.rn.f16x2.f32 %0, %1, %2;" : "=r"(r) : "f"(hi), "f"(lo)); return r;
}

// tf32: D += A(16x8) B(8x8)
__device__ __forceinline__ void mma8(float c[4], const uu a[4], const uu b[2]) {
    asm("mma.sync.aligned.m16n8k8.row.col.f32.tf32.tf32.f32 "
        "{%0,%1,%2,%3}, {%4,%5,%6,%7}, {%8,%9}, {%0,%1,%2,%3};"
        : "+f"(c[0]), "+f"(c[1]), "+f"(c[2]), "+f"(c[3])
        : "r"(a[0]), "r"(a[1]), "r"(a[2]), "r"(a[3]), "r"(b[0]), "r"(b[1]));
}
// fp16: D += A(16x16) B(16x8), fp32 accum
__device__ __forceinline__ void mma16(float c[4], const uu a[4], const uu b[2]) {
    asm("mma.sync.aligned.m16n8k16.row.col.f32.f16.f16.f32 "
        "{%0,%1,%2,%3}, {%4,%5,%6,%7}, {%8,%9}, {%0,%1,%2,%3};"
        : "+f"(c[0]), "+f"(c[1]), "+f"(c[2]), "+f"(c[3])
        : "r"(a[0]), "r"(a[1]), "r"(a[2]), "r"(a[3]), "r"(b[0]), "r"(b[1]));
}

__device__ __forceinline__ void barg(int id) {
    asm volatile("bar.sync %0, %1;" :: "r"(id), "r"(128) : "memory");
}
__device__ __forceinline__ void cpa16(void* s, const void* g) {
    unsigned sa = (unsigned)__cvta_generic_to_shared(s);
    asm volatile("cp.async.ca.shared.global [%0], [%1], 16;" :: "r"(sa), "l"(g));
}
__device__ __forceinline__ void cpa_commit() {
    asm volatile("cp.async.commit_group;" ::: "memory");
}
__device__ __forceinline__ void cpa_wait0() {
    asm volatile("cp.async.wait_group 0;" ::: "memory");
}
__device__ __forceinline__ void cpa_wait1() {
    asm volatile("cp.async.wait_group 1;" ::: "memory");
}

// ========== W pre-convert: fp32 -> tf32 bits [m][k][n], scale + bias comp folded ==========
__global__ void wconv_kernel(const float* __restrict__ Wq,
                             const float* __restrict__ Wk,
                             const float* __restrict__ Wv)
{
    int idx = blockIdx.x * 256 + threadIdx.x;      // 0..196607
    int m = idx >> 16, j = idx & 65535;
    const float* W = (m == 0) ? Wq : (m == 1 ? Wk : Wv);
    float sc = (m == 0) ? (SCALE * LOG2E * COMP) : COMP;
    g_wt[idx] = f2tf(W[j] * sc);
}

// ================= QKV projection (tf32 mainloop, fp16 epilogue) =================
#define PKC 32
#define XS_ST 36
#define WS_ST 196

__global__ void __launch_bounds__(128, 2) qkv_kernel(const float* __restrict__ x)
{
    extern __shared__ float smf[];
    float* xsb = smf;
    uu* wsb = (uu*)(smf + 2 * 64 * XS_ST);

    const int tid = threadIdx.x;
    const int w = tid >> 5, lane = tid & 31, gr = lane >> 2, t = lane & 3;
    const int row0 = blockIdx.x * 64;

    float acc[4][6][4];
#pragma unroll
    for (int rb = 0; rb < 4; rb++)
#pragma unroll
        for (int nt = 0; nt < 6; nt++)
#pragma unroll
            for (int c = 0; c < 4; c++) acc[rb][nt][c] = 0.f;

    auto issue = [&](int k0, int s) {
        float* xs = xsb + s * 64 * XS_ST;
        uu* ws = wsb + s * PKC * WS_ST;
#pragma unroll
        for (int it = 0; it < 4; it++) {
            int idx = tid + it * 128;
            int r = idx >> 3, c = (idx & 7) * 4;
            cpa16(&xs[r * XS_ST + c], &x[(size_t)(row0 + r) * En + k0 + c]);
        }
#pragma unroll
        for (int it = 0; it < 12; it++) {
            int idx = tid + it * 128;
            int kk = idx / 48, n4 = (idx % 48) * 4;
            int m = n4 >> 6, col = n4 & 63;
            cpa16(&ws[kk * WS_ST + n4], &g_wt[(size_t)m * En * Hn + (size_t)(k0 + kk) * Hn + col]);
        }
    };

    issue(0, 0);
    cpa_commit();

    for (int it = 0; it < En / PKC; it++) {
        __syncthreads();
        if (it + 1 < En / PKC) issue((it + 1) * PKC, (it + 1) & 1);
        cpa_commit();
        cpa_wait1();
        __syncthreads();

        const uu* xs = (const uu*)(xsb + (it & 1) * 64 * XS_ST);   // raw f32 bits
        const uu* ws = wsb + (it & 1) * PKC * WS_ST;
#pragma unroll
        for (int kk = 0; kk < PKC / 8; kk++) {
            uu a[4][4];
#pragma unroll
            for (int rb = 0; rb < 4; rb++) {
                int r = rb * 16 + gr;
                a[rb][0] = xs[r * XS_ST + kk * 8 + t];
                a[rb][1] = xs[(r + 8) * XS_ST + kk * 8 + t];
                a[rb][2] = xs[r * XS_ST + kk * 8 + t + 4];
                a[rb][3] = xs[(r + 8) * XS_ST + kk * 8 + t + 4];
            }
#pragma unroll
            for (int nt = 0; nt < 6; nt++) {
                int n0 = w * 48 + nt * 8;
                uu b[2];
                b[0] = ws[(kk * 8 + t) * WS_ST + n0 + gr];
                b[1] = ws[(kk * 8 + t + 4) * WS_ST + n0 + gr];
#pragma unroll
                for (int rb = 0; rb < 4; rb++) mma8(acc[rb][nt], a[rb], b);
            }
        }
    }

    // ---- epilogue: fp16x2 words in attn-ready layouts ----
    const int bb = row0 >> 12;
    const int tok0 = row0 & 4095;
#pragma unroll
    for (int nt = 0; nt < 6; nt++) {
        int n = w * 48 + nt * 8 + 2 * t;   // even; warp-uniform branch (8-aligned blocks)
        if (n < 128) {
            uu* base = (n < 64) ? g_q16 : g_k16;
            int hh = n & 63;
            // word sigma within 16-col group: logical word j=(nt&1)*4+t -> pos
            int wi = ((hh >> 4) << 3) + ((nt & 1) ? 2 * t + 1 : 2 * t);
#pragma unroll
            for (int rb = 0; rb < 4; rb++) {
                size_t r = (size_t)(row0 + rb * 16 + gr);
                base[r * 32 + wi]       = pkf16(acc[rb][nt][1], acc[rb][nt][0]);
                base[(r + 8) * 32 + wi] = pkf16(acc[rb][nt][3], acc[rb][nt][2]);
            }
        } else {
            int h0 = n - 128;   // even
            uu* r0p = g_vt16 + ((size_t)bb * Hn + h0) * (Tn / 2);
            uu* r1p = r0p + (Tn / 2);
#pragma unroll
            for (int rb = 0; rb < 4; rb++) {
                float n0 = __shfl_down_sync(~0u, acc[rb][nt][0], 4);
                float n1 = __shfl_down_sync(~0u, acc[rb][nt][1], 4);
                float n2 = __shfl_down_sync(~0u, acc[rb][nt][2], 4);
                float n3 = __shfl_down_sync(~0u, acc[rb][nt][3], 4);
                if (!(gr & 1)) {
                    int wb = (tok0 + rb * 16) >> 1;    // 8-word sigma group base
                    // sigma: toks (tk,tk+1) -> pos gr ; toks (tk+8,tk+9) -> pos gr+1
                    r0p[wb + gr]     = pkf16(n0, acc[rb][nt][0]);
                    r0p[wb + gr + 1] = pkf16(n2, acc[rb][nt][2]);
                    r1p[wb + gr]     = pkf16(n1, acc[rb][nt][1]);
                    r1p[wb + gr + 1] = pkf16(n3, acc[rb][nt][3]);
                }
            }
        }
    }
}

// ======== Flash attention: fp16 m16n8k16, 256 blocks, no-max ex2 softmax ========
// 3 kt-groups x (2x2) 32x32 warp tiles. Tiles are fp16x2 words, 32 words/row,
// smem stride 40 words (conflict-free LDS.64 frags). Merge buffers fp32, separate.
#define KST 40      // words per smem tile row
#define AS2 72      // fp32 merge stride
#define NG 3
#define STAGE_W (64 * KST)          // 2560 words per strip
#define MERGE_OFF (7 * STAGE_W)     // merge region starts after 7 strips

__global__ void __launch_bounds__(384, 1) attn_kernel(float* __restrict__ out)
{
    extern __shared__ uu sm[];
    const int tid = threadIdx.x;
    const int w = tid >> 5, lane = tid & 31, gr = lane >> 2, t = lane & 3;
    const int g = w >> 2, wq = w & 3;
    const int rw = wq >> 1, cw = wq & 1;
    const int tg = tid & 127;

    uu* qs  = sm;                                 // strip 0: Q tile
    uu* ksg = sm + (size_t)(1 + g) * STAGE_W;     // strips 1..3: K per group
    uu* vts = sm + (size_t)(4 + g) * STAGE_W;     // strips 4..6: V^T per group
    float* mbase = (float*)(sm + MERGE_OFF);      // 6 fp32 merge strips
    float* Mg = mbase + (size_t)(2 * g + cw) * 64 * AS2;

    const int b = blockIdx.x & 3;
    const int qt = 63 - (blockIdx.x >> 2);        // heavy q-tiles launch first
    const uu* kg  = g_k16  + (size_t)b * Tn * 32;
    const uu* vtb = g_vt16 + (size_t)b * Hn * (Tn / 2);

    const int rbase = rw * 32;
    const int cwords = cw * 16;                   // key-word base of this col strip

    // Q tile: bit-copy, 64 rows x 32 words (8KB)
    const uu* qg = g_q16 + ((size_t)b * Tn + qt * 64) * 32;
    for (int idx = tid; idx < 512; idx += 384)
        cpa16(&qs[(idx >> 3) * KST + (idx & 7) * 4], qg + idx * 4);
    cpa_commit();
    cpa_wait0();
    __syncthreads();

    float o[2][8][4];
    float ll[2][2];
#pragma unroll
    for (int rb = 0; rb < 2; rb++) {
        ll[rb][0] = ll[rb][1] = 0.f;
#pragma unroll
        for (int ht = 0; ht < 8; ht++)
#pragma unroll
            for (int c = 0; c < 4; c++) o[rb][ht][c] = 0.f;
    }

    for (int kt = g; kt <= qt; kt += NG) {
        barg(g + 1);   // group's readers done with ksg/vts
        const uu* kp = kg + (size_t)kt * 64 * 32;
#pragma unroll
        for (int it = 0; it < 4; it++) {
            int idx = tg + it * 128;
            int r = idx >> 3, c4 = (idx & 7) * 4;
            cpa16(&ksg[r * KST + c4], kp + idx * 4);
            cpa16(&vts[r * KST + c4], vtb + (size_t)r * (Tn / 2) + kt * 32 + c4);
        }
        cpa_commit();
        cpa_wait0();
        barg(g + 1);   // tiles visible to whole group

        // ---- stage 1: S(32x32) = Q K^T, fp16 k16 (uint2 frags) ----
        float s[2][4][4];
#pragma unroll
        for (int rb = 0; rb < 2; rb++)
#pragma unroll
            for (int nt = 0; nt < 4; nt++)
#pragma unroll
                for (int c = 0; c < 4; c++) s[rb][nt][c] = 0.f;
#pragma unroll
        for (int kk = 0; kk < 4; kk++) {          // k16 per step, H=64
            uu qa[2][4];
#pragma unroll
            for (int rb = 0; rb < 2; rb++) {
                int ra = (rbase + rb * 16 + gr) * KST + kk * 8 + 2 * t;
                uint2 u0 = *(const uint2*)&qs[ra];            // (a0, a2)
                uint2 u1 = *(const uint2*)&qs[ra + 8 * KST];  // (a1, a3)
                qa[rb][0] = u0.x; qa[rb][1] = u1.x;
                qa[rb][2] = u0.y; qa[rb][3] = u1.y;
            }
#pragma unroll
            for (int nt = 0; nt < 4; nt++) {
                uint2 kb = *(const uint2*)&ksg[(cw * 32 + nt * 8 + gr) * KST + kk * 8 + 2 * t];
                uu bf[2] = { kb.x, kb.y };
                mma16(s[0][nt], qa[0], bf);
                mma16(s[1][nt], qa[1], bf);
            }
        }

        if (kt == qt) {   // causal mask on diagonal tile
#pragma unroll
            for (int rb = 0; rb < 2; rb++) {
                int r0 = rbase + rb * 16 + gr, r1 = r0 + 8;
#pragma unroll
                for (int nt = 0; nt < 4; nt++) {
                    int c0 = cw * 32 + nt * 8 + 2 * t;
                    if (c0 > r0)     s[rb][nt][0] = -1e30f;
                    if (c0 + 1 > r0) s[rb][nt][1] = -1e30f;
                    if (c0 > r1)     s[rb][nt][2] = -1e30f;
                    if (c0 + 1 > r1) s[rb][nt][3] = -1e30f;
                }
            }
        }

        // ---- no-max softmax: p = ex2(s); pack to fp16x2 (key pairs) ----
        uu ps[2][4][2];
#pragma unroll
        for (int rb = 0; rb < 2; rb++) {
            float rs0 = 0.f, rs1 = 0.f;
#pragma unroll
            for (int nt = 0; nt < 4; nt++) {
                float p0 = ex2(s[rb][nt][0]), p1 = ex2(s[rb][nt][1]);
                float p2 = ex2(s[rb][nt][2]), p3 = ex2(s[rb][nt][3]);
                rs0 += p0 + p1; rs1 += p2 + p3;
                ps[rb][nt][0] = pkf16(p1, p0);
                ps[rb][nt][1] = pkf16(p3, p2);
            }
            rs0 += __shfl_xor_sync(~0u, rs0, 1);
            rs0 += __shfl_xor_sync(~0u, rs0, 2);
            rs1 += __shfl_xor_sync(~0u, rs1, 1);
            rs1 += __shfl_xor_sync(~0u, rs1, 2);
            ll[rb][0] += rs0;
            ll[rb][1] += rs1;
        }

        // ---- stage 2: O += P V, fp16 k16 (P a-frags from ps, V^T uint2) ----
#pragma unroll
        for (int kk = 0; kk < 2; kk++) {
            uu pa[2][4];
#pragma unroll
            for (int rb = 0; rb < 2; rb++) {
                pa[rb][0] = ps[rb][2 * kk][0];
                pa[rb][1] = ps[rb][2 * kk][1];
                pa[rb][2] = ps[rb][2 * kk + 1][0];
                pa[rb][3] = ps[rb][2 * kk + 1][1];
            }
#pragma unroll
            for (int ht = 0; ht < 8; ht++) {
                uint2 vv = *(const uint2*)&vts[(ht * 8 + gr) * KST + cwords + kk * 8 + 2 * t];
                uu vb[2] = { vv.x, vv.y };
                mma16(o[0][ht], pa[0], vb);
                mma16(o[1][ht], pa[1], vb);
            }
        }
    }

    // ---- dump 6 partials into merge strips ----
    __syncthreads();
#pragma unroll
    for (int rb = 0; rb < 2; rb++) {
        int r0 = rbase + rb * 16 + gr, r1 = r0 + 8;
#pragma unroll
        for (int ht = 0; ht < 8; ht++) {
            *(float2*)&Mg[r0 * AS2 + ht * 8 + 2 * t] = make_float2(o[rb][ht][0], o[rb][ht][1]);
            *(float2*)&Mg[r1 * AS2 + ht * 8 + 2 * t] = make_float2(o[rb][ht][2], o[rb][ht][3]);
        }
        if (t == 0) {
            Mg[r0 * AS2 + 64] = ll[rb][0];
            Mg[r1 * AS2 + 64] = ll[rb][1];
        }
    }
    __syncthreads();

    // ---- combine 6 partials (plain sums), write output ----
    float* ob = out + ((size_t)b * Tn + qt * 64) * Hn;
    for (int idx = tid; idx < 1024; idx += 384) {
        int r = idx >> 4, c4 = (idx & 15) * 4;
        float L = 0.f;
        float4 acc = make_float4(0.f, 0.f, 0.f, 0.f);
#pragma unroll
        for (int i = 0; i < 6; i++) {
            const float* Mi = mbase + (size_t)i * 64 * AS2;
            L += Mi[r * AS2 + 64];
            float4 v = *(const float4*)&Mi[r * AS2 + c4];
            acc.x += v.x; acc.y += v.y; acc.z += v.z; acc.w += v.w;
        }
        float inv = 1.f / L;
        acc.x *= inv; acc.y *= inv; acc.z *= inv; acc.w *= inv;
        *(float4*)&ob[(size_t)r * Hn + c4] = acc;
    }
}

// ================= launcher =================
extern "C" void kernel_launch(void* const* d_in, const int* in_sizes, int n_in,
                              void* d_out, int out_size)
{
    const float* x  = (const float*)d_in[0];
    const float* Wq = (const float*)d_in[1];
    const float* Wk = (const float*)d_in[2];
    const float* Wv = (const float*)d_in[3];
    float* out = (float*)d_out;

    wconv_kernel<<<768, 256>>>(Wq, Wk, Wv);

    int qkv_smem = 2 * (64 * XS_ST + PKC * WS_ST) * (int)sizeof(float);   // 68608
    cudaFuncSetAttribute(qkv_kernel, cudaFuncAttributeMaxDynamicSharedMemorySize, qkv_smem);
    qkv_kernel<<<(Bn * Tn) / 64, 128, qkv_smem>>>(x);

    int attn_smem = MERGE_OFF * 4 + 6 * 64 * AS2 * 4;                     // 182272
    cudaFuncSetAttribute(attn_kernel, cudaFuncAttributeMaxDynamicSharedMemorySize, attn_smem);
    attn_kernel<<<Bn * 64, 384, attn_smem>>>(out);
}

// round 17
// speedup vs baseline: 1.9173x; 1.1713x over previous
#include <cuda_runtime.h>

#define Bn 4
#define Tn 4096
#define En 1024
#define Hn 64
#define SCALE 0.03125f   // 1024^-0.5
#define LOG2E 1.44269504088896340736f

typedef unsigned uu;

// Projected tensors as fp16x2 words (written by qkv_kernel epilogue):
//  g_q16[b][tok][32w]  (SCALE*log2e folded, h word-sigma-permuted, pairs along h)
//  g_k16[b][tok][32w]  (h word-sigma-permuted, pairs along h)
//  g_vt16[b][h][2048w] (transposed, pairs along tokens, token word-sigma-permuted)
__device__ uu g_q16[Bn * Tn * 32];
__device__ uu g_k16[Bn * Tn * 32];
__device__ uu g_vt16[Bn * Hn * (Tn / 2)];
// W as fp16x2 words: [m][kpair(512)][n(64)], k-even in lo half; q pre-scaled
__device__ uu g_wt16[3 * 512 * 64];

__device__ __forceinline__ float ex2(float x) {
    float r; asm("ex2.approx.f32 %0, %1;" : "=f"(r) : "f"(x)); return r;
}
// pack two f32 into f16x2 (first arg -> upper/hi half)
__device__ __forceinline__ uu pkf16(float hi, float lo) {
    uu r; asm("cvt.rn.f16x2.f32 %0, %1, %2;" : "=r"(r) : "f"(hi), "f"(lo)); return r;
}

// fp16: D += A(16x16) B(16x8), fp32 accum
__device__ __forceinline__ void mma16(float c[4], const uu a[4], const uu b[2]) {
    asm("mma.sync.aligned.m16n8k16.row.col.f32.f16.f16.f32 "
        "{%0,%1,%2,%3}, {%4,%5,%6,%7}, {%8,%9}, {%0,%1,%2,%3};"
        : "+f"(c[0]), "+f"(c[1]), "+f"(c[2]), "+f"(c[3])
        : "r"(a[0]), "r"(a[1]), "r"(a[2]), "r"(a[3]), "r"(b[0]), "r"(b[1]));
}

__device__ __forceinline__ void barg(int id) {
    asm volatile("bar.sync %0, %1;" :: "r"(id), "r"(128) : "memory");
}
__device__ __forceinline__ void cpa16(void* s, const void* g) {
    unsigned sa = (unsigned)__cvta_generic_to_shared(s);
    asm volatile("cp.async.ca.shared.global [%0], [%1], 16;" :: "r"(sa), "l"(g));
}
__device__ __forceinline__ void cpa_commit() {
    asm volatile("cp.async.commit_group;" ::: "memory");
}
__device__ __forceinline__ void cpa_wait0() {
    asm volatile("cp.async.wait_group 0;" ::: "memory");
}
__device__ __forceinline__ void cpa_wait1() {
    asm volatile("cp.async.wait_group 1;" ::: "memory");
}

// ========== W pre-convert: fp32 -> fp16x2 words [m][kpair][n], q-scale folded ==========
__global__ void wconv_kernel(const float* __restrict__ Wq,
                             const float* __restrict__ Wk,
                             const float* __restrict__ Wv)
{
    int idx = blockIdx.x * 256 + threadIdx.x;      // 0..98303
    int m = idx >> 15, rem = idx & 32767;
    int kp = rem >> 6, n = rem & 63;
    const float* W = (m == 0) ? Wq : (m == 1 ? Wk : Wv);
    float sc = (m == 0) ? (SCALE * LOG2E) : 1.f;
    float w0 = W[(2 * kp) * Hn + n] * sc;          // k even -> lo
    float w1 = W[(2 * kp + 1) * Hn + n] * sc;      // k odd  -> hi
    g_wt16[idx] = pkf16(w1, w0);
}

// ================= QKV projection: fp16 m16n8k16 mainloop =================
// 256 blocks x 128 thr, 3 blocks/SM. x: register-prefetch LDG -> pkf16 -> STS.
// W: cp.async of pre-packed fp16 words. Fragment k-remap (words 2t,2t+1).
#define PKC 32
#define XST16 24    // 16 data words + 8 pad; frag banks 24*gr+2t conflict-free per phase
#define WST16 196

__global__ void __launch_bounds__(128, 3) qkv_kernel(const float* __restrict__ x)
{
    extern __shared__ uu sm16[];
    uu* xsb = sm16;                        // 2 stages x [64][XST16]
    uu* wsb = sm16 + 2 * 64 * XST16;       // 2 stages x [16][WST16]

    const int tid = threadIdx.x;
    const int w = tid >> 5, lane = tid & 31, gr = lane >> 2, t = lane & 3;
    const int row0 = blockIdx.x * 64;

    float acc[4][6][4];
#pragma unroll
    for (int rb = 0; rb < 4; rb++)
#pragma unroll
        for (int nt = 0; nt < 6; nt++)
#pragma unroll
            for (int c = 0; c < 4; c++) acc[rb][nt][c] = 0.f;

    float4 xreg[4];
    auto ldx = [&](int k0) {
#pragma unroll
        for (int it = 0; it < 4; it++) {
            int idx = tid + it * 128;
            int r = idx >> 3, c = (idx & 7) * 4;
            xreg[it] = *(const float4*)&x[(size_t)(row0 + r) * En + k0 + c];
        }
    };
    auto stx = [&](int s) {
        uu* xs = xsb + s * 64 * XST16;
#pragma unroll
        for (int it = 0; it < 4; it++) {
            int idx = tid + it * 128;
            int r = idx >> 3, woff = (idx & 7) * 2;
            uint2 u = make_uint2(pkf16(xreg[it].y, xreg[it].x),
                                 pkf16(xreg[it].w, xreg[it].z));
            *(uint2*)&xs[r * XST16 + woff] = u;
        }
    };
    auto issueW = [&](int k0, int s) {
        uu* ws = wsb + s * 16 * WST16;
        int kp0 = k0 >> 1;
#pragma unroll
        for (int it = 0; it < 6; it++) {
            int idx = tid + it * 128;
            int kpl = idx / 48, n4 = (idx % 48) * 4;
            int m = n4 >> 6, col = n4 & 63;
            cpa16(&ws[kpl * WST16 + n4],
                  &g_wt16[(size_t)m * 32768 + (size_t)(kp0 + kpl) * 64 + col]);
        }
    };

    ldx(0);
    issueW(0, 0);
    cpa_commit();

    for (int it = 0; it < En / PKC; it++) {
        __syncthreads();                    // all warps done computing iter it-1
        stx(it & 1);                        // stage it (last read at iter it-2)
        if (it + 1 < En / PKC) {
            ldx((it + 1) * PKC);
            issueW((it + 1) * PKC, (it + 1) & 1);
        }
        cpa_commit();
        cpa_wait1();                        // W chunk it resident
        __syncthreads();                    // x + W stage visible

        const uu* xs = xsb + (it & 1) * 64 * XST16;
        const uu* ws = wsb + (it & 1) * 16 * WST16;
#pragma unroll
        for (int kk = 0; kk < 2; kk++) {    // 2 x k16 per 32-chunk
            uu a[4][4];
#pragma unroll
            for (int rb = 0; rb < 4; rb++) {
                int r = rb * 16 + gr;
                uint2 u0 = *(const uint2*)&xs[r * XST16 + kk * 8 + 2 * t];
                uint2 u1 = *(const uint2*)&xs[(r + 8) * XST16 + kk * 8 + 2 * t];
                a[rb][0] = u0.x; a[rb][1] = u1.x;
                a[rb][2] = u0.y; a[rb][3] = u1.y;
            }
#pragma unroll
            for (int nt = 0; nt < 6; nt++) {
                int n0 = w * 48 + nt * 8;
                uu b[2];
                b[0] = ws[(kk * 8 + 2 * t) * WST16 + n0 + gr];
                b[1] = ws[(kk * 8 + 2 * t + 1) * WST16 + n0 + gr];
#pragma unroll
                for (int rb = 0; rb < 4; rb++) mma16(acc[rb][nt], a[rb], b);
            }
        }
    }

    // ---- epilogue: fp16x2 words in attn-ready layouts ----
    const int bb = row0 >> 12;
    const int tok0 = row0 & 4095;
#pragma unroll
    for (int nt = 0; nt < 6; nt++) {
        int n = w * 48 + nt * 8 + 2 * t;   // even; warp-uniform branch (8-aligned blocks)
        if (n < 128) {
            uu* base = (n < 64) ? g_q16 : g_k16;
            int hh = n & 63;
            // word sigma within 16-col group: logical word j=(nt&1)*4+t -> pos
            int wi = ((hh >> 4) << 3) + ((nt & 1) ? 2 * t + 1 : 2 * t);
#pragma unroll
            for (int rb = 0; rb < 4; rb++) {
                size_t r = (size_t)(row0 + rb * 16 + gr);
                base[r * 32 + wi]       = pkf16(acc[rb][nt][1], acc[rb][nt][0]);
                base[(r + 8) * 32 + wi] = pkf16(acc[rb][nt][3], acc[rb][nt][2]);
            }
        } else {
            int h0 = n - 128;   // even
            uu* r0p = g_vt16 + ((size_t)bb * Hn + h0) * (Tn / 2);
            uu* r1p = r0p + (Tn / 2);
#pragma unroll
            for (int rb = 0; rb < 4; rb++) {
                float n0 = __shfl_down_sync(~0u, acc[rb][nt][0], 4);
                float n1 = __shfl_down_sync(~0u, acc[rb][nt][1], 4);
                float n2 = __shfl_down_sync(~0u, acc[rb][nt][2], 4);
                float n3 = __shfl_down_sync(~0u, acc[rb][nt][3], 4);
                if (!(gr & 1)) {
                    int wb = (tok0 + rb * 16) >> 1;    // 8-word sigma group base
                    r0p[wb + gr]     = pkf16(n0, acc[rb][nt][0]);
                    r0p[wb + gr + 1] = pkf16(n2, acc[rb][nt][2]);
                    r1p[wb + gr]     = pkf16(n1, acc[rb][nt][1]);
                    r1p[wb + gr + 1] = pkf16(n3, acc[rb][nt][3]);
                }
            }
        }
    }
}

// ======== Flash attention (R16 verbatim): fp16 m16n8k16, no-max ex2 softmax ========
#define KST 40      // words per smem tile row
#define AS2 72      // fp32 merge stride
#define NG 3
#define STAGE_W (64 * KST)          // 2560 words per strip
#define MERGE_OFF (7 * STAGE_W)     // merge region starts after 7 strips

__global__ void __launch_bounds__(384, 1) attn_kernel(float* __restrict__ out)
{
    extern __shared__ uu sm[];
    const int tid = threadIdx.x;
    const int w = tid >> 5, lane = tid & 31, gr = lane >> 2, t = lane & 3;
    const int g = w >> 2, wq = w & 3;
    const int rw = wq >> 1, cw = wq & 1;
    const int tg = tid & 127;

    uu* qs  = sm;                                 // strip 0: Q tile
    uu* ksg = sm + (size_t)(1 + g) * STAGE_W;     // strips 1..3: K per group
    uu* vts = sm + (size_t)(4 + g) * STAGE_W;     // strips 4..6: V^T per group
    float* mbase = (float*)(sm + MERGE_OFF);      // 6 fp32 merge strips
    float* Mg = mbase + (size_t)(2 * g + cw) * 64 * AS2;

    const int b = blockIdx.x & 3;
    const int qt = 63 - (blockIdx.x >> 2);        // heavy q-tiles launch first
    const uu* kg  = g_k16  + (size_t)b * Tn * 32;
    const uu* vtb = g_vt16 + (size_t)b * Hn * (Tn / 2);

    const int rbase = rw * 32;
    const int cwords = cw * 16;                   // key-word base of this col strip

    // Q tile: bit-copy, 64 rows x 32 words (8KB)
    const uu* qg = g_q16 + ((size_t)b * Tn + qt * 64) * 32;
    for (int idx = tid; idx < 512; idx += 384)
        cpa16(&qs[(idx >> 3) * KST + (idx & 7) * 4], qg + idx * 4);
    cpa_commit();
    cpa_wait0();
    __syncthreads();

    float o[2][8][4];
    float ll[2][2];
#pragma unroll
    for (int rb = 0; rb < 2; rb++) {
        ll[rb][0] = ll[rb][1] = 0.f;
#pragma unroll
        for (int ht = 0; ht < 8; ht++)
#pragma unroll
            for (int c = 0; c < 4; c++) o[rb][ht][c] = 0.f;
    }

    for (int kt = g; kt <= qt; kt += NG) {
        barg(g + 1);   // group's readers done with ksg/vts
        const uu* kp = kg + (size_t)kt * 64 * 32;
#pragma unroll
        for (int it = 0; it < 4; it++) {
            int idx = tg + it * 128;
            int r = idx >> 3, c4 = (idx & 7) * 4;
            cpa16(&ksg[r * KST + c4], kp + idx * 4);
            cpa16(&vts[r * KST + c4], vtb + (size_t)r * (Tn / 2) + kt * 32 + c4);
        }
        cpa_commit();
        cpa_wait0();
        barg(g + 1);   // tiles visible to whole group

        // ---- stage 1: S(32x32) = Q K^T, fp16 k16 (uint2 frags) ----
        float s[2][4][4];
#pragma unroll
        for (int rb = 0; rb < 2; rb++)
#pragma unroll
            for (int nt = 0; nt < 4; nt++)
#pragma unroll
                for (int c = 0; c < 4; c++) s[rb][nt][c] = 0.f;
#pragma unroll
        for (int kk = 0; kk < 4; kk++) {          // k16 per step, H=64
            uu qa[2][4];
#pragma unroll
            for (int rb = 0; rb < 2; rb++) {
                int ra = (rbase + rb * 16 + gr) * KST + kk * 8 + 2 * t;
                uint2 u0 = *(const uint2*)&qs[ra];            // (a0, a2)
                uint2 u1 = *(const uint2*)&qs[ra + 8 * KST];  // (a1, a3)
                qa[rb][0] = u0.x; qa[rb][1] = u1.x;
                qa[rb][2] = u0.y; qa[rb][3] = u1.y;
            }
#pragma unroll
            for (int nt = 0; nt < 4; nt++) {
                uint2 kb = *(const uint2*)&ksg[(cw * 32 + nt * 8 + gr) * KST + kk * 8 + 2 * t];
                uu bf[2] = { kb.x, kb.y };
                mma16(s[0][nt], qa[0], bf);
                mma16(s[1][nt], qa[1], bf);
            }
        }

        if (kt == qt) {   // causal mask on diagonal tile
#pragma unroll
            for (int rb = 0; rb < 2; rb++) {
                int r0 = rbase + rb * 16 + gr, r1 = r0 + 8;
#pragma unroll
                for (int nt = 0; nt < 4; nt++) {
                    int c0 = cw * 32 + nt * 8 + 2 * t;
                    if (c0 > r0)     s[rb][nt][0] = -1e30f;
                    if (c0 + 1 > r0) s[rb][nt][1] = -1e30f;
                    if (c0 > r1)     s[rb][nt][2] = -1e30f;
                    if (c0 + 1 > r1) s[rb][nt][3] = -1e30f;
                }
            }
        }

        // ---- no-max softmax: p = ex2(s); pack to fp16x2 (key pairs) ----
        uu ps[2][4][2];
#pragma unroll
        for (int rb = 0; rb < 2; rb++) {
            float rs0 = 0.f, rs1 = 0.f;
#pragma unroll
            for (int nt = 0; nt < 4; nt++) {
                float p0 = ex2(s[rb][nt][0]), p1 = ex2(s[rb][nt][1]);
                float p2 = ex2(s[rb][nt][2]), p3 = ex2(s[rb][nt][3]);
                rs0 += p0 + p1; rs1 += p2 + p3;
                ps[rb][nt][0] = pkf16(p1, p0);
                ps[rb][nt][1] = pkf16(p3, p2);
            }
            rs0 += __shfl_xor_sync(~0u, rs0, 1);
            rs0 += __shfl_xor_sync(~0u, rs0, 2);
            rs1 += __shfl_xor_sync(~0u, rs1, 1);
            rs1 += __shfl_xor_sync(~0u, rs1, 2);
            ll[rb][0] += rs0;
            ll[rb][1] += rs1;
        }

        // ---- stage 2: O += P V, fp16 k16 (P a-frags from ps, V^T uint2) ----
#pragma unroll
        for (int kk = 0; kk < 2; kk++) {
            uu pa[2][4];
#pragma unroll
            for (int rb = 0; rb < 2; rb++) {
                pa[rb][0] = ps[rb][2 * kk][0];
                pa[rb][1] = ps[rb][2 * kk][1];
                pa[rb][2] = ps[rb][2 * kk + 1][0];
                pa[rb][3] = ps[rb][2 * kk + 1][1];
            }
#pragma unroll
            for (int ht = 0; ht < 8; ht++) {
                uint2 vv = *(const uint2*)&vts[(ht * 8 + gr) * KST + cwords + kk * 8 + 2 * t];
                uu vb[2] = { vv.x, vv.y };
                mma16(o[0][ht], pa[0], vb);
                mma16(o[1][ht], pa[1], vb);
            }
        }
    }

    // ---- dump 6 partials into merge strips ----
    __syncthreads();
#pragma unroll
    for (int rb = 0; rb < 2; rb++) {
        int r0 = rbase + rb * 16 + gr, r1 = r0 + 8;
#pragma unroll
        for (int ht = 0; ht < 8; ht++) {
            *(float2*)&Mg[r0 * AS2 + ht * 8 + 2 * t] = make_float2(o[rb][ht][0], o[rb][ht][1]);
            *(float2*)&Mg[r1 * AS2 + ht * 8 + 2 * t] = make_float2(o[rb][ht][2], o[rb][ht][3]);
        }
        if (t == 0) {
            Mg[r0 * AS2 + 64] = ll[rb][0];
            Mg[r1 * AS2 + 64] = ll[rb][1];
        }
    }
    __syncthreads();

    // ---- combine 6 partials (plain sums), write output ----
    float* ob = out + ((size_t)b * Tn + qt * 64) * Hn;
    for (int idx = tid; idx < 1024; idx += 384) {
        int r = idx >> 4, c4 = (idx & 15) * 4;
        float L = 0.f;
        float4 acc = make_float4(0.f, 0.f, 0.f, 0.f);
#pragma unroll
        for (int i = 0; i < 6; i++) {
            const float* Mi = mbase + (size_t)i * 64 * AS2;
            L += Mi[r * AS2 + 64];
            float4 v = *(const float4*)&Mi[r * AS2 + c4];
            acc.x += v.x; acc.y += v.y; acc.z += v.z; acc.w += v.w;
        }
        float inv = 1.f / L;
        acc.x *= inv; acc.y *= inv; acc.z *= inv; acc.w *= inv;
        *(float4*)&ob[(size_t)r * Hn + c4] = acc;
    }
}

// ================= launcher =================
extern "C" void kernel_launch(void* const* d_in, const int* in_sizes, int n_in,
                              void* d_out, int out_size)
{
    const float* x  = (const float*)d_in[0];
    const float* Wq = (const float*)d_in[1];
    const float* Wk = (const float*)d_in[2];
    const float* Wv = (const float*)d_in[3];
    float* out = (float*)d_out;

    wconv_kernel<<<384, 256>>>(Wq, Wk, Wv);

    int qkv_smem = (2 * 64 * XST16 + 2 * 16 * WST16) * (int)sizeof(uu);   // 37376
    cudaFuncSetAttribute(qkv_kernel, cudaFuncAttributeMaxDynamicSharedMemorySize, qkv_smem);
    qkv_kernel<<<(Bn * Tn) / 64, 128, qkv_smem>>>(x);

    int attn_smem = MERGE_OFF * 4 + 6 * 64 * AS2 * 4;                     // 182272
    cudaFuncSetAttribute(attn_kernel, cudaFuncAttributeMaxDynamicSharedMemorySize, attn_smem);
    attn_kernel<<<Bn * 64, 384, attn_smem>>>(out);
}